// round 16
// baseline (speedup 1.0000x reference)
#include <cuda_runtime.h>

#define VV   400000
#define DD   200
#define CC   45
#define BSN  4096      // B*S
#define KN   12
#define KC   10
#define KT   22

// ---- kernel 2 config ----
#define TT    32       // tokens per block (grid 128)
#define NT2   384      // 12 warps = 6 c-groups x 2 t-halves; lane = k
#define SSTR  201      // sStage row stride (floats): bank step 9, conflict-free transpose reads
#define XSTR  34       // sXT row stride (floats): 32 tokens + 2 pad, f2-aligned
#define RSTR  1537     // sR lane stride (floats): odd -> conflict-free staging
#define NVAL  1536     // 12 warps x 128 staged values

// scratch: feat [4096, 200]
__device__ float g_feat[BSN * DD];

// ============================================================
// Kernel 1: masked gather + mean  -> g_feat
// ============================================================
__global__ __launch_bounds__(128) void feat_kernel(
    const int* __restrict__ ng_ids, const int* __restrict__ ng_mask,
    const int* __restrict__ cx_ids, const int* __restrict__ cx_mask,
    const float* __restrict__ embed)
{
    const int tok = blockIdx.x;
    const int tid = threadIdx.x;

    __shared__ int raw_ids[KT], raw_msk[KT];
    __shared__ int s_ids[KT];
    __shared__ int s_n;
    __shared__ float s_inv;

    if (tid < KN) {
        raw_ids[tid] = ng_ids[tok * KN + tid];
        raw_msk[tid] = ng_mask[tok * KN + tid];
    } else if (tid < KT) {
        const int j = tid - KN;
        raw_ids[tid] = cx_ids[tok * KC + j];
        raw_msk[tid] = cx_mask[tok * KC + j];
    }
    __syncthreads();

    if (tid == 0) {
        int n = 0;
        #pragma unroll
        for (int i = 0; i < KT; i++)
            if (raw_msk[i]) s_ids[n++] = raw_ids[i];
        s_n = n;
        s_inv = 1.0f / (float)(n > 0 ? n : 1);
    }
    __syncthreads();

    const int n = s_n;
    const float inv = s_inv;

    if (tid < DD / 2) {
        float sx = 0.f, sy = 0.f;
        #pragma unroll 4
        for (int i = 0; i < n; i++) {
            const long long row = (long long)s_ids[i] * DD;
            const float2 v = *(const float2*)&embed[row + tid * 2];
            sx += v.x; sy += v.y;
        }
        *(float2*)&g_feat[(long long)tok * DD + tid * 2] = make_float2(sx * inv, sy * inv);
    }
}

// ============================================================
// Kernel 2: windowed matmul, lane = k (zero lane-duplication)
//   X transposed in smem: sXT[k][t]  (k = 0..1023, rows >=1000 zeroed)
//   x: LDS.64 per token-pair, distinct addr per lane -> 2-wf floor
//   w: coalesced LDG.32 (L1/L2 resident)
//   acc: f32x2 packed over token pairs; lane-reduce staged via smem.
// ============================================================
__device__ __forceinline__ void ffma2(unsigned long long& d,
                                      unsigned long long a,
                                      unsigned long long b)
{
    asm volatile("fma.rn.f32x2 %0, %1, %2, %0;" : "+l"(d) : "l"(a), "l"(b));
}

extern __shared__ float smem2[];

__global__ __launch_bounds__(NT2, 1) void gemm_kernel(
    const float* __restrict__ W, const float* __restrict__ bias,
    float* __restrict__ out)
{
    float* sStage = smem2;                    // 36 x 201 floats
    float* sXT    = smem2 + 36 * SSTR;        // 1024 x 34 floats
    float* sR     = smem2;                    // reduce staging (overlays, after barrier)

    const int tid  = threadIdx.x;
    const int t0   = blockIdx.x * TT;
    const int b0   = t0 >> 7;                 // sequence index (per-seq zero pad)
    const int lane = tid & 31;
    const int wid  = tid >> 5;                // 0..11

    // ---- 1. fill staging tile: rows t0-2 .. t0+33, seq-masked ----
    {
        const float4* feat4 = (const float4*)g_feat;
        for (int i = tid; i < 36 * 50; i += NT2) {
            const int row = i / 50;
            const int q   = i - row * 50;
            const int g   = t0 + row - 2;
            float4 v = make_float4(0.f, 0.f, 0.f, 0.f);
            if ((g >> 7) == b0) v = feat4[g * 50 + q];
            float* dst = sStage + row * SSTR + q * 4;
            dst[0] = v.x; dst[1] = v.y; dst[2] = v.z; dst[3] = v.w;
        }
    }
    __syncthreads();

    // ---- 2. transpose into sXT[k][t]; zero k in [1000,1024) ----
    {
        // window(t)[k] = feat_pad[t-2 + k/200][k%200] = sStage[t + k/200][k%200]
        for (int kk = wid; kk < 1000; kk += 12) {
            const int r = kk / 200;
            const int d = kk - r * 200;
            const float v = sStage[(lane + r) * SSTR + d];  // bank step 9: conflict-free
            sXT[kk * XSTR + lane] = v;                      // bank step 1: conflict-free
        }
        for (int i = tid; i < 24 * XSTR; i += NT2)
            sXT[1000 * XSTR + i] = 0.f;
    }
    __syncthreads();

    // ---- 3. main loop ----
    const int cg = wid >> 1;                  // 0..5
    const int tg = wid & 1;                   // 0..1
    const int cbase = cg * 8;

    int joff[8];
    #pragma unroll
    for (int j = 0; j < 8; j++) {
        int cj = cbase + j;
        if (cj > CC - 1) cj = CC - 1;         // clamp pad rows (discarded at store)
        joff[j] = cj * 1000;
    }

    unsigned long long acc[8][8];
    #pragma unroll
    for (int j = 0; j < 8; j++)
        #pragma unroll
        for (int i = 0; i < 8; i++) acc[j][i] = 0ull;

    const unsigned long long* xb =
        (const unsigned long long*)sXT + (long long)lane * 17 + tg * 8;
    const float* wb = W + lane;

    #pragma unroll 1
    for (int km = 0; km < 32; km++) {
        const int  k   = km * 32 + lane;
        const bool kin = (k < 1000);

        unsigned long long xv[8];
        const unsigned long long* xq = xb + km * 544;   // 32 rows * 17 ull
        #pragma unroll
        for (int i = 0; i < 8; i++) xv[i] = xq[i];

        #pragma unroll
        for (int j = 0; j < 8; j++) {
            const float wv = kin ? __ldg(wb + joff[j] + km * 32) : 0.f;
            unsigned long long wd;
            asm("mov.b64 %0, {%1, %1};" : "=l"(wd) : "f"(wv));
            #pragma unroll
            for (int i = 0; i < 8; i++)
                ffma2(acc[j][i], xv[i], wd);
        }
    }
    __syncthreads();

    // ---- 4. stage partials column-major: sR[lane][wid*128 + v] ----
    {
        float* dst = sR + (long long)lane * RSTR + wid * 128;
        #pragma unroll
        for (int j = 0; j < 8; j++)
            #pragma unroll
            for (int i = 0; i < 8; i++) {
                const unsigned long long a = acc[j][i];
                dst[(j * 8 + i) * 2 + 0] = __uint_as_float((unsigned)(a & 0xffffffffull));
                dst[(j * 8 + i) * 2 + 1] = __uint_as_float((unsigned)(a >> 32));
            }
    }
    __syncthreads();

    // ---- 5. lane-reduce + bias + store ----
    for (int r = tid; r < NVAL; r += NT2) {
        float s = 0.f;
        #pragma unroll
        for (int l = 0; l < 32; l++)
            s += sR[l * RSTR + r];
        const int w   = r >> 7;
        const int v   = r & 127;
        const int j   = v >> 4;
        const int i   = (v >> 1) & 7;
        const int p   = v & 1;
        const int c   = (w >> 1) * 8 + j;
        if (c < CC) {
            const int t = t0 + (w & 1) * 16 + 2 * i + p;
            out[t * CC + c] = s + bias[c];
        }
    }
}

// ============================================================
extern "C" void kernel_launch(void* const* d_in, const int* in_sizes, int n_in,
                              void* d_out, int out_size)
{
    const int*   ng_ids  = (const int*)d_in[0];
    const int*   ng_mask = (const int*)d_in[1];
    const int*   cx_ids  = (const int*)d_in[2];
    const int*   cx_mask = (const int*)d_in[3];
    const float* embed   = (const float*)d_in[4];
    const float* W       = (const float*)d_in[5];
    const float* bias    = (const float*)d_in[6];
    float*       out     = (float*)d_out;

    feat_kernel<<<BSN, 128>>>(ng_ids, ng_mask, cx_ids, cx_mask, embed);

    // smem = max(fill phase 168,208 B, reduce staging 32*1537*4 = 196,736 B)
    const size_t smem = (size_t)32 * RSTR * sizeof(float);   // 196,736
    cudaFuncSetAttribute(gemm_kernel, cudaFuncAttributeMaxDynamicSharedMemorySize, (int)smem);
    gemm_kernel<<<BSN / TT, NT2, smem>>>(W, bias, out);
}